// round 16
// baseline (speedup 1.0000x reference)
#include <cuda_runtime.h>
#include <cuda_fp16.h>
#include <cstdint>

#define BB 256
#define TT 256
#define CC 1024
#define LL 64
#define SS 129          // 2L+1
#define GW 80           // emit width (halves): 64 labels + blank@64 + pad
#define CH 16           // time-rows per chunk; 16*80*2B = 2560B = 5 f4/lane
#define NCHUNK (TT / CH)                // 16
#define NBUF 4                          // cp.async pipeline depth
#define TCH 64                          // producer gating granularity (t rows)
#define NTC (TT / TCH)                  // 4 counters
#define CBLK 128                        // consumer blocks (2 batches each)
#define PBLK ((BB * TT) / 8)            // 8192 producer blocks, 8 rows each
#define EPSF 1e-7f
#define LN2F 0.69314718055994530942f
#define PSCALE 1048576.0f               // 2^20: lifts p into fp16 normal range

// scratch (no allocation allowed -> __device__ globals)
__device__ __align__(16) __half g_buf[(size_t)BB * TT * GW];  // p * 2^20, fp16
__device__ int done_ctr[NTC];           // rows completed per 64-t block

__device__ __forceinline__ float flog2(float x) {
    float y; asm("lg2.approx.ftz.f32 %0, %1;" : "=f"(y) : "f"(x)); return y;
}
__device__ __forceinline__ bool detect_i64(const int* yt, int lane) {
    return __all_sync(0xffffffffu, yt[2 * lane + 1] == 0);
}
__device__ __forceinline__ int load_lab(const int* yt, bool is64, int idx) {
    int v = is64 ? yt[2 * idx] : yt[idx];
    return min(max(v, 0), CC - 1);              // clamp: safety net
}

__global__ void k_zero() { if (threadIdx.x < NTC) done_ctr[threadIdx.x] = 0; }

// ---------------------------------------------------------------------------
// producer warp: ONE (b,t) row, rows ordered (t-chunk64, b, t-within) -- the
// R13-proven full-bandwidth ordering.  One-shot blocks keep MLP maximal.
// softmax(log(y+EPS)) = (y+EPS)/sum(y+EPS): one plain sum + divide.
// ---------------------------------------------------------------------------
__device__ __forceinline__ void produce_row(const float* __restrict__ yp,
                                            const int*   __restrict__ yt,
                                            int W, int lane, bool is64) {
    int t = ((W >> 14) << 6) | (W & 63);        // (chunk, b, t-within) decode
    int b = (W >> 6) & (BB - 1);
    size_t rowi = (size_t)b * TT + t;

    const float*  row  = yp + rowi * CC;
    const float4* row4 = (const float4*)row;

    float s = 0.f;
    #pragma unroll
    for (int k = 0; k < 8; ++k) {               // 8 coalesced float4 per lane
        float4 v = row4[lane + 32 * k];
        s += (v.x + v.y) + (v.z + v.w);
    }
    #pragma unroll
    for (int o = 16; o; o >>= 1) s += __shfl_xor_sync(0xffffffffu, s, o);

    float invZ = PSCALE / (s + (float)CC * EPSF);   // fold 2^20 into divide

    int lab0 = load_lab(yt, is64, b * LL + 2 * lane);
    int lab1 = load_lab(yt, is64, b * LL + 2 * lane + 1);
    __half2 v01 = __floats2half2_rn((row[lab0] + EPSF) * invZ,
                                    (row[lab1] + EPSF) * invZ);

    __half2* go2 = (__half2*)(g_buf + rowi * GW);
    go2[lane] = v01;                            // labels 2*lane, 2*lane+1
    if (lane < 8) {                             // j = 64..79: blank + zero pad
        __half2 z = __floats2half2_rn(
            (lane == 0) ? (row[CC - 1] + EPSF) * invZ : 0.f, 0.f);
        go2[32 + lane] = z;
    }

    __syncwarp();                               // lanes' stores issued
    __threadfence();                            // release
    if (lane == 0) atomicAdd(&done_ctr[t >> 6], 1);
}

// ---------------------------------------------------------------------------
// consumer: alpha recursion, LINEAR domain a_new = (a1+a2+skip*a3)*p.  One
// warp per batch, 5 states/thread, 2 shuffles/step, 4-deep cp.async pipeline.
// Blank states share one broadcast LDS; renorm every 8 steps via redux.sync.
// Gates each 64-t block on done_ctr (coarse: no fine-grained races).
// ---------------------------------------------------------------------------
__device__ __forceinline__ void wait_tc(int tc, int lane) {
    if (lane == 0) {
        volatile int* p = &done_ctr[tc];
        while (*p < TCH * BB) __nanosleep(128);
    }
    __syncwarp();
    __threadfence();                            // acquire
}
__device__ __forceinline__ void issue_chunk(const float4* gsrc,
                                            unsigned int sdst, int lane) {
    #pragma unroll
    for (int k = 0; k < (CH * GW * 2) / (16 * 32); ++k) {   // 5 iters
        int i4 = lane + 32 * k;
        asm volatile("cp.async.ca.shared.global [%0], [%1], 16;\n"
                     :: "r"(sdst + 16u * i4), "l"(gsrc + i4));
    }
    asm volatile("cp.async.commit_group;\n" ::: "memory");
}
template <int N>
__device__ __forceinline__ void wait_cp() {
    asm volatile("cp.async.wait_group %0;\n" :: "n"(N) : "memory");
    __syncwarp();
}

__device__ __forceinline__ void step_row(const __half* __restrict__ srow,
                                         const bool* __restrict__ islab,
                                         const int* __restrict__ lidx,
                                         const float* __restrict__ skipm,
                                         float* __restrict__ a, int lane) {
    float pb = __half2float(srow[64]);          // blank: one broadcast LDS
    float p[5];
    #pragma unroll
    for (int i = 0; i < 5; ++i)
        p[i] = islab[i] ? __half2float(srow[lidx[i]]) : pb;

    float q4 = __shfl_up_sync(0xffffffffu, a[4], 1);   // state 5*lane-1
    float q3 = __shfl_up_sync(0xffffffffu, a[3], 1);   // state 5*lane-2
    if (lane == 0) { q4 = 0.0f; q3 = 0.0f; }

    float n0 = (a[0] + q4   + skipm[0] * q3  ) * p[0];
    float n1 = (a[1] + a[0] + skipm[1] * q4  ) * p[1];
    float n2 = (a[2] + a[1] + skipm[2] * a[0]) * p[2];
    float n3 = (a[3] + a[2] + skipm[3] * a[1]) * p[3];
    float n4 = (a[4] + a[3] + skipm[4] * a[2]) * p[4];
    a[0] = n0; a[1] = n1; a[2] = n2; a[3] = n3; a[4] = n4;
}

__device__ __forceinline__ void renorm(float* __restrict__ a, float& acc) {
    float m = fmaxf(fmaxf(fmaxf(a[0], a[1]), fmaxf(a[2], a[3])), a[4]);
    unsigned int mu = __float_as_uint(m);       // positive floats: order-safe
    asm("redux.sync.max.u32 %0, %1, 0xffffffff;" : "=r"(mu) : "r"(mu));
    int ebits = (int)((mu >> 23) & 0xFFu);
    float scale = __int_as_float((254 - ebits) << 23);  // 2^-(e-127)
    acc += (float)(ebits - 127);
    #pragma unroll
    for (int i = 0; i < 5; ++i) a[i] *= scale;
}

__global__ void k_fused(const float* __restrict__ yp,
                        const int*   __restrict__ yt,
                        float* __restrict__ out) {
    __shared__ __align__(16) __half sm[2][NBUF][CH * GW];  // 20,480 B

    int w    = threadIdx.x >> 5;
    int lane = threadIdx.x & 31;
    bool is64 = detect_i64(yt, lane);

    if (blockIdx.x >= CBLK) {                   // ---------- producer role
        produce_row(yp, yt, (blockIdx.x - CBLK) * 8 + w, lane, is64);
        return;
    }
    if (w >= 2) return;                         // consumer: warps 0,1 only

    // ---------- consumer role: batch b per warp
    int b = blockIdx.x * 2 + w;

    bool  islab[5];
    int   lidx[5];
    float skipm[5];
    #pragma unroll
    for (int i = 0; i < 5; ++i) {
        int s    = 5 * lane + i;
        bool odd = (s & 1);
        islab[i] = odd || (s >= SS);            // invalid -> slot 66 (p=0)
        lidx[i]  = (odd && s < SS) ? ((s - 1) >> 1) : 66;
        skipm[i] = 0.0f;
        if (s < SS && odd && s >= 3) {          // pos>=2 and label state
            int j = (s - 1) >> 1;               // j >= 1 here
            skipm[i] = (load_lab(yt, is64, b * LL + j) !=
                        load_lab(yt, is64, b * LL + j - 1)) ? 1.0f : 0.0f;
        }
    }

    const float4* gb4 = (const float4*)(g_buf + (size_t)b * TT * GW);
    const int C4 = (CH * GW * 2) / 16;          // float4 per chunk = 160
    unsigned int sb[NBUF];
    #pragma unroll
    for (int i = 0; i < NBUF; ++i)
        sb[i] = (unsigned int)__cvta_generic_to_shared(&sm[w][i][0]);

    // t-chunk 0 covers alpha chunks 0..3: wait once, prime whole pipeline
    wait_tc(0, lane);
    #pragma unroll
    for (int c = 0; c < NBUF; ++c) issue_chunk(gb4 + c * C4, sb[c], lane);

    float a[5];
    float acc = 0.0f;                           // accumulated log2 scale

    #pragma unroll 1
    for (int c = 0; c < NCHUNK; ++c) {
        wait_cp<NBUF - 1>();                    // <=3 outstanding -> chunk c done
        const __half* sbuf = &sm[w][c & (NBUF - 1)][0];

        if (c == 0) {                           // init at t=0 (scaled p)
            float pb0 = __half2float(sbuf[64]);
            #pragma unroll
            for (int i = 0; i < 5; ++i) {
                int s = 5 * lane + i;
                float pi = islab[i] ? __half2float(sbuf[lidx[i]]) : pb0;
                a[i] = (s < 2) ? pi : 0.0f;
            }
            #pragma unroll
            for (int r = 1; r < CH; ++r) {
                step_row(sbuf + r * GW, islab, lidx, skipm, a, lane);
                if ((r & 7) == 7) renorm(a, acc);
            }
        } else {
            #pragma unroll
            for (int r = 0; r < CH; ++r) {
                step_row(sbuf + r * GW, islab, lidx, skipm, a, lane);
                if ((r & 7) == 7) renorm(a, acc);
            }
        }

        if (c + NBUF < NCHUNK) {                // refill slot: gate on producer
            wait_tc((c + NBUF) >> 2, lane);     // 64-t block of chunk c+4
            issue_chunk(gb4 + (size_t)(c + NBUF) * C4,
                        sb[(c + NBUF) & (NBUF - 1)], lane);
        } else {
            asm volatile("cp.async.commit_group;\n" ::: "memory"); // keep count
        }
    }

    // states 127 (i=2) and 128 (i=3) live in lane 25.
    // 256 emit factors each carried 2^20 -> subtract 20*256 from the exponent.
    if (lane == 25) {
        float s = a[2] + a[3];                  // tail sum, linear
        out[b] = -(flog2(s) + acc - 20.0f * 256.0f) * LN2F;
    }
}

// ---------------------------------------------------------------------------
extern "C" void kernel_launch(void* const* d_in, const int* in_sizes, int n_in,
                              void* d_out, int out_size) {
    // y_pred is by far the larger buffer; robust to metadata ordering.
    const float* yp;
    const int*   yt;
    if (in_sizes[0] > in_sizes[1]) {
        yp = (const float*)d_in[0];
        yt = (const int*)d_in[1];
    } else {
        yp = (const float*)d_in[1];
        yt = (const int*)d_in[0];
    }
    float* out = (float*)d_out;

    k_zero<<<1, 32>>>();                        // reset the 4 gate counters
    k_fused<<<CBLK + PBLK, 256>>>(yp, yt, out); // consumers first, then producers
}

// round 17
// speedup vs baseline: 1.2808x; 1.2808x over previous
#include <cuda_runtime.h>
#include <cuda_fp16.h>
#include <cstdint>

#define BB 256
#define TT 256
#define CC 1024
#define LL 64
#define SS 129          // 2L+1
#define GW 80           // emit width (halves): 64 labels + blank@64 + pad
#define CH 16           // time-rows per chunk; 16*80*2B = 2560B = 5 f4/lane
#define NCHUNK (TT / CH)                // 16
#define NBUF 4                          // cp.async pipeline depth
#define TCH 64                          // producer gating granularity (t rows)
#define NTC (TT / TCH)                  // 4 counters
#define CBLK 128                        // consumer blocks (2 batches each)
#define PBLK ((BB * TT) / 8)            // 8192 producer blocks, 8 rows each
#define EPSF 1e-7f
#define LN2F 0.69314718055994530942f
#define PSCALE 1048576.0f               // 2^20: lifts p into fp16 normal range

// scratch (no allocation allowed -> __device__ globals)
__device__ __align__(16) __half g_buf[(size_t)BB * TT * GW];  // p * 2^20, fp16
__device__ int done_ctr[NTC];           // rows completed per 64-t block

__device__ __forceinline__ float flog2(float x) {
    float y; asm("lg2.approx.ftz.f32 %0, %1;" : "=f"(y) : "f"(x)); return y;
}
__device__ __forceinline__ bool detect_i64(const int* yt, int lane) {
    return __all_sync(0xffffffffu, yt[2 * lane + 1] == 0);
}
__device__ __forceinline__ int load_lab(const int* yt, bool is64, int idx) {
    int v = is64 ? yt[2 * idx] : yt[idx];
    return min(max(v, 0), CC - 1);              // clamp: safety net
}

__global__ void k_zero() { if (threadIdx.x < NTC) done_ctr[threadIdx.x] = 0; }

// ---------------------------------------------------------------------------
// producer warp: ONE (b,t) row, (t-chunk64, b, t-within) ordering -- byte-
// identical math to the R13-proven full-bandwidth kernel.  Signaling is
// block-level: __syncthreads + ONE red.release (NO __threadfence -> no L1
// flush, which is what killed fusions #1-#3).
// ---------------------------------------------------------------------------
__device__ __forceinline__ void produce_row(const float* __restrict__ yp,
                                            const int*   __restrict__ yt,
                                            int W, int lane, bool is64) {
    int t = ((W >> 14) << 6) | (W & 63);        // (chunk, b, t-within) decode
    int b = (W >> 6) & (BB - 1);
    size_t rowi = (size_t)b * TT + t;

    const float*  row  = yp + rowi * CC;
    const float4* row4 = (const float4*)row;

    float s = 0.f;
    #pragma unroll
    for (int k = 0; k < 8; ++k) {               // 8 coalesced float4 per lane
        float4 v = row4[lane + 32 * k];
        s += (v.x + v.y) + (v.z + v.w);
    }
    #pragma unroll
    for (int o = 16; o; o >>= 1) s += __shfl_xor_sync(0xffffffffu, s, o);

    float invZ = PSCALE / (s + (float)CC * EPSF);   // fold 2^20 into divide

    int lab0 = load_lab(yt, is64, b * LL + 2 * lane);
    int lab1 = load_lab(yt, is64, b * LL + 2 * lane + 1);
    __half2 v01 = __floats2half2_rn((row[lab0] + EPSF) * invZ,
                                    (row[lab1] + EPSF) * invZ);

    __half2* go2 = (__half2*)(g_buf + rowi * GW);
    go2[lane] = v01;                            // labels 2*lane, 2*lane+1
    if (lane < 8) {                             // j = 64..79: blank + zero pad
        __half2 z = __floats2half2_rn(
            (lane == 0) ? (row[CC - 1] + EPSF) * invZ : 0.f, 0.f);
        go2[32 + lane] = z;
    }
}

// ---------------------------------------------------------------------------
// consumer: alpha recursion, LINEAR domain a_new = (a1+a2+skip*a3)*p.  One
// warp per batch, 5 states/thread, 2 shuffles/step, 4-deep cp.async pipeline,
// blank-broadcast LDS, renorm every 8 steps (redux.sync).  Gates each 64-t
// block on done_ctr via ld.acquire (no full fence).
// ---------------------------------------------------------------------------
__device__ __forceinline__ void wait_tc(int tc, int lane) {
    if (lane == 0) {
        int v;
        do {
            asm volatile("ld.acquire.gpu.global.s32 %0, [%1];"
                         : "=r"(v) : "l"(&done_ctr[tc]) : "memory");
            if (v >= TCH * BB) break;
            __nanosleep(128);
        } while (true);
    }
    __syncwarp();
}
__device__ __forceinline__ void issue_chunk(const float4* gsrc,
                                            unsigned int sdst, int lane) {
    #pragma unroll
    for (int k = 0; k < (CH * GW * 2) / (16 * 32); ++k) {   // 5 iters
        int i4 = lane + 32 * k;
        asm volatile("cp.async.ca.shared.global [%0], [%1], 16;\n"
                     :: "r"(sdst + 16u * i4), "l"(gsrc + i4));
    }
    asm volatile("cp.async.commit_group;\n" ::: "memory");
}
template <int N>
__device__ __forceinline__ void wait_cp() {
    asm volatile("cp.async.wait_group %0;\n" :: "n"(N) : "memory");
    __syncwarp();
}

__device__ __forceinline__ void step_row(const __half* __restrict__ srow,
                                         const bool* __restrict__ islab,
                                         const int* __restrict__ lidx,
                                         const float* __restrict__ skipm,
                                         float* __restrict__ a, int lane) {
    float pb = __half2float(srow[64]);          // blank: one broadcast LDS
    float p[5];
    #pragma unroll
    for (int i = 0; i < 5; ++i)
        p[i] = islab[i] ? __half2float(srow[lidx[i]]) : pb;

    float q4 = __shfl_up_sync(0xffffffffu, a[4], 1);   // state 5*lane-1
    float q3 = __shfl_up_sync(0xffffffffu, a[3], 1);   // state 5*lane-2
    if (lane == 0) { q4 = 0.0f; q3 = 0.0f; }

    float n0 = (a[0] + q4   + skipm[0] * q3  ) * p[0];
    float n1 = (a[1] + a[0] + skipm[1] * q4  ) * p[1];
    float n2 = (a[2] + a[1] + skipm[2] * a[0]) * p[2];
    float n3 = (a[3] + a[2] + skipm[3] * a[1]) * p[3];
    float n4 = (a[4] + a[3] + skipm[4] * a[2]) * p[4];
    a[0] = n0; a[1] = n1; a[2] = n2; a[3] = n3; a[4] = n4;
}

__device__ __forceinline__ void renorm(float* __restrict__ a, float& acc) {
    float m = fmaxf(fmaxf(fmaxf(a[0], a[1]), fmaxf(a[2], a[3])), a[4]);
    unsigned int mu = __float_as_uint(m);       // positive floats: order-safe
    asm("redux.sync.max.u32 %0, %1, 0xffffffff;" : "=r"(mu) : "r"(mu));
    int ebits = (int)((mu >> 23) & 0xFFu);
    float scale = __int_as_float((254 - ebits) << 23);  // 2^-(e-127)
    acc += (float)(ebits - 127);
    #pragma unroll
    for (int i = 0; i < 5; ++i) a[i] *= scale;
}

__global__ void k_fused(const float* __restrict__ yp,
                        const int*   __restrict__ yt,
                        float* __restrict__ out) {
    __shared__ __align__(16) __half sm[2][NBUF][CH * GW];  // 20,480 B

    int w    = threadIdx.x >> 5;
    int lane = threadIdx.x & 31;
    bool is64 = detect_i64(yt, lane);

    if (blockIdx.x >= CBLK) {                   // ---------- producer role
        int W = (blockIdx.x - CBLK) * 8 + w;    // all 8 rows: same b, same t64
        produce_row(yp, yt, W, lane, is64);
        __syncthreads();                        // block's stores ordered (cta)
        if (threadIdx.x == 0) {                 // release WITHOUT L1 flush
            int t = ((W >> 14) << 6) | (W & 63);
            asm volatile("red.release.gpu.global.add.s32 [%0], %1;"
                         :: "l"(&done_ctr[t >> 6]), "r"(8) : "memory");
        }
        return;
    }
    if (w >= 2) return;                         // consumer: warps 0,1 only

    // ---------- consumer role: batch b per warp
    int b = blockIdx.x * 2 + w;

    bool  islab[5];
    int   lidx[5];
    float skipm[5];
    #pragma unroll
    for (int i = 0; i < 5; ++i) {
        int s    = 5 * lane + i;
        bool odd = (s & 1);
        islab[i] = odd || (s >= SS);            // invalid -> slot 66 (p=0)
        lidx[i]  = (odd && s < SS) ? ((s - 1) >> 1) : 66;
        skipm[i] = 0.0f;
        if (s < SS && odd && s >= 3) {          // pos>=2 and label state
            int j = (s - 1) >> 1;               // j >= 1 here
            skipm[i] = (load_lab(yt, is64, b * LL + j) !=
                        load_lab(yt, is64, b * LL + j - 1)) ? 1.0f : 0.0f;
        }
    }

    const float4* gb4 = (const float4*)(g_buf + (size_t)b * TT * GW);
    const int C4 = (CH * GW * 2) / 16;          // float4 per chunk = 160
    unsigned int sb[NBUF];
    #pragma unroll
    for (int i = 0; i < NBUF; ++i)
        sb[i] = (unsigned int)__cvta_generic_to_shared(&sm[w][i][0]);

    // t-chunk 0 covers alpha chunks 0..3: wait once, prime whole pipeline
    wait_tc(0, lane);
    #pragma unroll
    for (int c = 0; c < NBUF; ++c) issue_chunk(gb4 + c * C4, sb[c], lane);

    float a[5];
    float acc = 0.0f;                           // accumulated log2 scale

    #pragma unroll 1
    for (int c = 0; c < NCHUNK; ++c) {
        wait_cp<NBUF - 1>();                    // <=3 outstanding -> chunk c done
        const __half* sbuf = &sm[w][c & (NBUF - 1)][0];

        if (c == 0) {                           // init at t=0 (scaled p)
            float pb0 = __half2float(sbuf[64]);
            #pragma unroll
            for (int i = 0; i < 5; ++i) {
                int s = 5 * lane + i;
                float pi = islab[i] ? __half2float(sbuf[lidx[i]]) : pb0;
                a[i] = (s < 2) ? pi : 0.0f;
            }
            #pragma unroll
            for (int r = 1; r < CH; ++r) {
                step_row(sbuf + r * GW, islab, lidx, skipm, a, lane);
                if ((r & 7) == 7) renorm(a, acc);
            }
        } else {
            #pragma unroll
            for (int r = 0; r < CH; ++r) {
                step_row(sbuf + r * GW, islab, lidx, skipm, a, lane);
                if ((r & 7) == 7) renorm(a, acc);
            }
        }

        if (c + NBUF < NCHUNK) {                // refill slot: gate on producer
            wait_tc((c + NBUF) >> 2, lane);     // 64-t block of chunk c+4
            issue_chunk(gb4 + (size_t)(c + NBUF) * C4,
                        sb[(c + NBUF) & (NBUF - 1)], lane);
        } else {
            asm volatile("cp.async.commit_group;\n" ::: "memory"); // keep count
        }
    }

    // states 127 (i=2) and 128 (i=3) live in lane 25.
    // 256 emit factors each carried 2^20 -> subtract 20*256 from the exponent.
    if (lane == 25) {
        float s = a[2] + a[3];                  // tail sum, linear
        out[b] = -(flog2(s) + acc - 20.0f * 256.0f) * LN2F;
    }
}

// ---------------------------------------------------------------------------
extern "C" void kernel_launch(void* const* d_in, const int* in_sizes, int n_in,
                              void* d_out, int out_size) {
    // y_pred is by far the larger buffer; robust to metadata ordering.
    const float* yp;
    const int*   yt;
    if (in_sizes[0] > in_sizes[1]) {
        yp = (const float*)d_in[0];
        yt = (const int*)d_in[1];
    } else {
        yp = (const float*)d_in[1];
        yt = (const int*)d_in[0];
    }
    float* out = (float*)d_out;

    k_zero<<<1, 32>>>();                        // reset the 4 gate counters
    k_fused<<<CBLK + PBLK, 256>>>(yp, yt, out); // consumers first, then producers
}